// round 4
// baseline (speedup 1.0000x reference)
#include <cuda_runtime.h>
#include <cstdint>

// ---------------------------------------------------------------------------
// Coo2Cel: periodic minimum-image pair displacements within cutoff.
// Inputs: pos_xyz [B,N,3] f32, cel_mat [B,3,3] f32, pbc [B,3] i32, ent [B,N] i32
// Output (single f32 buffer): vec [B,N,N,3] ++ sod [B,N,N] ++ mask [B,N,N]
// ---------------------------------------------------------------------------

#define RC2 36.0f   // rc = 6.0
#define I_TILE 8

// SoA scratch for fractional coordinates (max B*N = 2*4096; padded)
__device__ float g_fx[16384];
__device__ float g_fy[16384];
__device__ float g_fz[16384];

__global__ void frac_kernel(const float* __restrict__ pos,
                            const float* __restrict__ cel,
                            int N, int B)
{
    int idx = blockIdx.x * blockDim.x + threadIdx.x;
    if (idx >= B * N) return;
    int b = idx / N;

    const float* m = cel + b * 9;
    float m00 = m[0], m01 = m[1], m02 = m[2];
    float m10 = m[3], m11 = m[4], m12 = m[5];
    float m20 = m[6], m21 = m[7], m22 = m[8];

    float det = m00 * (m11 * m22 - m12 * m21)
              - m01 * (m10 * m22 - m12 * m20)
              + m02 * (m10 * m21 - m11 * m20);
    float r = 1.0f / det;

    float i00 = (m11 * m22 - m12 * m21) * r;
    float i01 = (m02 * m21 - m01 * m22) * r;
    float i02 = (m01 * m12 - m02 * m11) * r;
    float i10 = (m12 * m20 - m10 * m22) * r;
    float i11 = (m00 * m22 - m02 * m20) * r;
    float i12 = (m02 * m10 - m00 * m12) * r;
    float i20 = (m10 * m21 - m11 * m20) * r;
    float i21 = (m01 * m20 - m00 * m21) * r;
    float i22 = (m00 * m11 - m01 * m10) * r;

    float p0 = pos[idx * 3 + 0];
    float p1 = pos[idx * 3 + 1];
    float p2 = pos[idx * 3 + 2];

    g_fx[idx] = p0 * i00 + p1 * i10 + p2 * i20;
    g_fy[idx] = p0 * i01 + p1 * i11 + p2 * i21;
    g_fz[idx] = p0 * i02 + p1 * i12 + p2 * i22;
}

// Each thread owns 4 consecutive j (kept in registers) and loops over
// I_TILE consecutive i's, amortizing all j-side loads across i.
__global__ void __launch_bounds__(128)
pair_kernel(const float* __restrict__ cel,
            const int*   __restrict__ pbc,
            const int*   __restrict__ ent,
            float* __restrict__ out,
            int N, int B)
{
    const int b  = blockIdx.z;
    const int i0 = blockIdx.y * I_TILE;
    const int j0 = (blockIdx.x * blockDim.x + threadIdx.x) * 4;
    if (j0 >= N) return;

    const float* c = cel + b * 9;
    const float c00 = c[0], c01 = c[1], c02 = c[2];
    const float c10 = c[3], c11 = c[4], c12 = c[5];
    const float c20 = c[6], c21 = c[7], c22 = c[8];

    const float pb0 = pbc[b * 3 + 0] ? 1.0f : 0.0f;
    const float pb1 = pbc[b * 3 + 1] ? 1.0f : 0.0f;
    const float pb2 = pbc[b * 3 + 2] ? 1.0f : 0.0f;

    const int base = b * N;

    // j-side data: loaded ONCE, reused for all I_TILE i's
    const float4 fx4 = *reinterpret_cast<const float4*>(g_fx + base + j0);
    const float4 fy4 = *reinterpret_cast<const float4*>(g_fy + base + j0);
    const float4 fz4 = *reinterpret_cast<const float4*>(g_fz + base + j0);
    const int4   ej4 = *reinterpret_cast<const int4*>(ent + base + j0);

    const float fjx[4] = { fx4.x, fx4.y, fx4.z, fx4.w };
    const float fjy[4] = { fy4.x, fy4.y, fy4.z, fy4.w };
    const float fjz[4] = { fz4.x, fz4.y, fz4.z, fz4.w };
    const bool  ej[4]  = { ej4.x != 0, ej4.y != 0, ej4.z != 0, ej4.w != 0 };

    const size_t NN       = (size_t)N * N;
    const size_t sod_off  = (size_t)B * NN * 3;
    const size_t mask_off = (size_t)B * NN * 4;

    #pragma unroll
    for (int t = 0; t < I_TILE; ++t) {
        const int i = i0 + t;

        // i-side scalars: warp-broadcast L1 hits (cheap)
        const float fi0 = g_fx[base + i];
        const float fi1 = g_fy[base + i];
        const float fi2 = g_fz[base + i];
        const bool  ent_i = ent[base + i] != 0;

        float vx[4], vy[4], vz[4], sd[4], mk[4];

        #pragma unroll
        for (int k = 0; k < 4; ++k) {
            const int j = j0 + k;
            float d0 = fjx[k] - fi0;
            float d1 = fjy[k] - fi1;
            float d2 = fjz[k] - fi2;
            d0 -= rintf(d0) * pb0;   // round-half-even, matches jnp.round
            d1 -= rintf(d1) * pb1;
            d2 -= rintf(d2) * pb2;

            float v0 = d0 * c00 + d1 * c10 + d2 * c20;
            float v1 = d0 * c01 + d1 * c11 + d2 * c21;
            float v2 = d0 * c02 + d1 * c12 + d2 * c22;
            float s  = v0 * v0 + v1 * v1 + v2 * v2;

            bool ok = ent_i && ej[k] && (i != j) && (s < RC2);
            vx[k] = ok ? v0 : 0.0f;
            vy[k] = ok ? v1 : 0.0f;
            vz[k] = ok ? v2 : 0.0f;
            sd[k] = ok ? s  : 0.0f;
            mk[k] = ok ? 1.0f : 0.0f;
        }

        const size_t pair = ((size_t)base + i) * N + j0;

        float4* vdst = reinterpret_cast<float4*>(out + pair * 3);
        vdst[0] = make_float4(vx[0], vy[0], vz[0], vx[1]);
        vdst[1] = make_float4(vy[1], vz[1], vx[2], vy[2]);
        vdst[2] = make_float4(vz[2], vx[3], vy[3], vz[3]);

        *reinterpret_cast<float4*>(out + sod_off + pair) =
            make_float4(sd[0], sd[1], sd[2], sd[3]);

        *reinterpret_cast<float4*>(out + mask_off + pair) =
            make_float4(mk[0], mk[1], mk[2], mk[3]);
    }
}

extern "C" void kernel_launch(void* const* d_in, const int* in_sizes, int n_in,
                              void* d_out, int out_size)
{
    const float* pos = (const float*)d_in[0];
    const float* cel = (const float*)d_in[1];
    const int*   pbc = (const int*)  d_in[2];
    const int*   ent = (const int*)  d_in[3];
    float* out = (float*)d_out;

    const int B = in_sizes[1] / 9;          // cel_mat has B*9 elements
    const int N = in_sizes[3] / B;          // ent has B*N elements

    {
        int total = B * N;
        int threads = 256;
        int blocks = (total + threads - 1) / threads;
        frac_kernel<<<blocks, threads>>>(pos, cel, N, B);
    }
    {
        dim3 threads(128, 1, 1);
        dim3 blocks((N + 128 * 4 - 1) / (128 * 4), (N + I_TILE - 1) / I_TILE, B);
        pair_kernel<<<blocks, threads>>>(cel, pbc, ent, out, N, B);
    }
}

// round 5
// speedup vs baseline: 1.2153x; 1.2153x over previous
#include <cuda_runtime.h>
#include <cstdint>

// ---------------------------------------------------------------------------
// Coo2Cel: periodic minimum-image pair displacements within cutoff.
// Inputs: pos_xyz [B,N,3] f32, cel_mat [B,3,3] f32, pbc [B,3] i32, ent [B,N] i32
// Output (single f32 buffer): vec [B,N,N,3] ++ sod [B,N,N] ++ mask [B,N,N]
// ---------------------------------------------------------------------------

#define RC2 36.0f   // rc = 6.0
#define I_TILE 4

// SoA scratch for fractional coordinates (max B*N = 2*4096; padded)
__device__ float g_fx[16384];
__device__ float g_fy[16384];
__device__ float g_fz[16384];

__global__ void frac_kernel(const float* __restrict__ pos,
                            const float* __restrict__ cel,
                            int N, int B)
{
    int idx = blockIdx.x * blockDim.x + threadIdx.x;
    if (idx >= B * N) return;
    int b = idx / N;

    const float* m = cel + b * 9;
    float m00 = m[0], m01 = m[1], m02 = m[2];
    float m10 = m[3], m11 = m[4], m12 = m[5];
    float m20 = m[6], m21 = m[7], m22 = m[8];

    float det = m00 * (m11 * m22 - m12 * m21)
              - m01 * (m10 * m22 - m12 * m20)
              + m02 * (m10 * m21 - m11 * m20);
    float r = 1.0f / det;

    float i00 = (m11 * m22 - m12 * m21) * r;
    float i01 = (m02 * m21 - m01 * m22) * r;
    float i02 = (m01 * m12 - m02 * m11) * r;
    float i10 = (m12 * m20 - m10 * m22) * r;
    float i11 = (m00 * m22 - m02 * m20) * r;
    float i12 = (m02 * m10 - m00 * m12) * r;
    float i20 = (m10 * m21 - m11 * m20) * r;
    float i21 = (m01 * m20 - m00 * m21) * r;
    float i22 = (m00 * m11 - m01 * m10) * r;

    float p0 = pos[idx * 3 + 0];
    float p1 = pos[idx * 3 + 1];
    float p2 = pos[idx * 3 + 2];

    g_fx[idx] = p0 * i00 + p1 * i10 + p2 * i20;
    g_fy[idx] = p0 * i01 + p1 * i11 + p2 * i21;
    g_fz[idx] = p0 * i02 + p1 * i12 + p2 * i22;
}

// Each thread owns 4 consecutive j (registers) and iterates over I_TILE
// consecutive i's in a ROLLED loop (unroll 1): steady-state store pipelining,
// low register pressure, j-side loads amortized across i.
__global__ void __launch_bounds__(256)
pair_kernel(const float* __restrict__ cel,
            const int*   __restrict__ pbc,
            const int*   __restrict__ ent,
            float* __restrict__ out,
            int N, int B)
{
    const int b  = blockIdx.z;
    const int i0 = blockIdx.y * I_TILE;
    const int j0 = (blockIdx.x * blockDim.x + threadIdx.x) * 4;
    if (j0 >= N) return;

    const float* c = cel + b * 9;
    const float c00 = c[0], c01 = c[1], c02 = c[2];
    const float c10 = c[3], c11 = c[4], c12 = c[5];
    const float c20 = c[6], c21 = c[7], c22 = c[8];

    const float pb0 = pbc[b * 3 + 0] ? 1.0f : 0.0f;
    const float pb1 = pbc[b * 3 + 1] ? 1.0f : 0.0f;
    const float pb2 = pbc[b * 3 + 2] ? 1.0f : 0.0f;

    const int base = b * N;

    // j-side data: loaded ONCE, reused for all I_TILE i's
    const float4 fx4 = *reinterpret_cast<const float4*>(g_fx + base + j0);
    const float4 fy4 = *reinterpret_cast<const float4*>(g_fy + base + j0);
    const float4 fz4 = *reinterpret_cast<const float4*>(g_fz + base + j0);
    const int4   ej4 = *reinterpret_cast<const int4*>(ent + base + j0);

    const float fjx[4] = { fx4.x, fx4.y, fx4.z, fx4.w };
    const float fjy[4] = { fy4.x, fy4.y, fy4.z, fy4.w };
    const float fjz[4] = { fz4.x, fz4.y, fz4.z, fz4.w };
    const bool  ej[4]  = { ej4.x != 0, ej4.y != 0, ej4.z != 0, ej4.w != 0 };

    const size_t NN       = (size_t)N * N;
    const size_t sod_off  = (size_t)B * NN * 3;
    const size_t mask_off = (size_t)B * NN * 4;

    #pragma unroll 1
    for (int t = 0; t < I_TILE; ++t) {
        const int i = i0 + t;

        // i-side scalars: warp-broadcast L1 hits (cheap)
        const float fi0 = g_fx[base + i];
        const float fi1 = g_fy[base + i];
        const float fi2 = g_fz[base + i];
        const bool  ent_i = ent[base + i] != 0;

        float vx[4], vy[4], vz[4], sd[4], mk[4];

        #pragma unroll
        for (int k = 0; k < 4; ++k) {
            const int j = j0 + k;
            float d0 = fjx[k] - fi0;
            float d1 = fjy[k] - fi1;
            float d2 = fjz[k] - fi2;
            d0 -= rintf(d0) * pb0;   // round-half-even, matches jnp.round
            d1 -= rintf(d1) * pb1;
            d2 -= rintf(d2) * pb2;

            float v0 = d0 * c00 + d1 * c10 + d2 * c20;
            float v1 = d0 * c01 + d1 * c11 + d2 * c21;
            float v2 = d0 * c02 + d1 * c12 + d2 * c22;
            float s  = v0 * v0 + v1 * v1 + v2 * v2;

            bool ok = ent_i && ej[k] && (i != j) && (s < RC2);
            vx[k] = ok ? v0 : 0.0f;
            vy[k] = ok ? v1 : 0.0f;
            vz[k] = ok ? v2 : 0.0f;
            sd[k] = ok ? s  : 0.0f;
            mk[k] = ok ? 1.0f : 0.0f;
        }

        const size_t pair = ((size_t)base + i) * N + j0;

        float4* vdst = reinterpret_cast<float4*>(out + pair * 3);
        vdst[0] = make_float4(vx[0], vy[0], vz[0], vx[1]);
        vdst[1] = make_float4(vy[1], vz[1], vx[2], vy[2]);
        vdst[2] = make_float4(vz[2], vx[3], vy[3], vz[3]);

        *reinterpret_cast<float4*>(out + sod_off + pair) =
            make_float4(sd[0], sd[1], sd[2], sd[3]);

        *reinterpret_cast<float4*>(out + mask_off + pair) =
            make_float4(mk[0], mk[1], mk[2], mk[3]);
    }
}

extern "C" void kernel_launch(void* const* d_in, const int* in_sizes, int n_in,
                              void* d_out, int out_size)
{
    const float* pos = (const float*)d_in[0];
    const float* cel = (const float*)d_in[1];
    const int*   pbc = (const int*)  d_in[2];
    const int*   ent = (const int*)  d_in[3];
    float* out = (float*)d_out;

    const int B = in_sizes[1] / 9;          // cel_mat has B*9 elements
    const int N = in_sizes[3] / B;          // ent has B*N elements

    {
        int total = B * N;
        int threads = 256;
        int blocks = (total + threads - 1) / threads;
        frac_kernel<<<blocks, threads>>>(pos, cel, N, B);
    }
    {
        dim3 threads(256, 1, 1);
        dim3 blocks((N + 256 * 4 - 1) / (256 * 4), (N + I_TILE - 1) / I_TILE, B);
        pair_kernel<<<blocks, threads>>>(cel, pbc, ent, out, N, B);
    }
}

// round 6
// speedup vs baseline: 1.7092x; 1.4063x over previous
#include <cuda_runtime.h>
#include <cstdint>

// ---------------------------------------------------------------------------
// Coo2Cel: periodic minimum-image pair displacements within cutoff.
// Inputs: pos_xyz [B,N,3] f32, cel_mat [B,3,3] f32, pbc [B,3] i32, ent [B,N] i32
// Output (single f32 buffer): vec [B,N,N,3] ++ sod [B,N,N] ++ mask [B,N,N]
//
// R6: stores staged in SMEM (STS.128) and drained by bulk-async (TMA) copies,
// bypassing the expensive STG.128 issue path (12 cyc/inst on sm_103a).
// ---------------------------------------------------------------------------

#define RC2 36.0f   // rc = 6.0
#define I_TILE 4
#define JBLK 512    // j's per block (128 threads x 4)

// SoA scratch for fractional coordinates (max B*N = 2*4096; padded)
__device__ float g_fx[16384];
__device__ float g_fy[16384];
__device__ float g_fz[16384];

__global__ void frac_kernel(const float* __restrict__ pos,
                            const float* __restrict__ cel,
                            int N, int B)
{
    int idx = blockIdx.x * blockDim.x + threadIdx.x;
    if (idx >= B * N) return;
    int b = idx / N;

    const float* m = cel + b * 9;
    float m00 = m[0], m01 = m[1], m02 = m[2];
    float m10 = m[3], m11 = m[4], m12 = m[5];
    float m20 = m[6], m21 = m[7], m22 = m[8];

    float det = m00 * (m11 * m22 - m12 * m21)
              - m01 * (m10 * m22 - m12 * m20)
              + m02 * (m10 * m21 - m11 * m20);
    float r = 1.0f / det;

    float i00 = (m11 * m22 - m12 * m21) * r;
    float i01 = (m02 * m21 - m01 * m22) * r;
    float i02 = (m01 * m12 - m02 * m11) * r;
    float i10 = (m12 * m20 - m10 * m22) * r;
    float i11 = (m00 * m22 - m02 * m20) * r;
    float i12 = (m02 * m10 - m00 * m12) * r;
    float i20 = (m10 * m21 - m11 * m20) * r;
    float i21 = (m01 * m20 - m00 * m21) * r;
    float i22 = (m00 * m11 - m01 * m10) * r;

    float p0 = pos[idx * 3 + 0];
    float p1 = pos[idx * 3 + 1];
    float p2 = pos[idx * 3 + 2];

    g_fx[idx] = p0 * i00 + p1 * i10 + p2 * i20;
    g_fy[idx] = p0 * i01 + p1 * i11 + p2 * i21;
    g_fz[idx] = p0 * i02 + p1 * i12 + p2 * i22;
}

__device__ __forceinline__ uint32_t smem_u32(const void* p) {
    uint32_t a;
    asm("{ .reg .u64 t; cvta.to.shared.u64 t, %1; cvt.u32.u64 %0, t; }"
        : "=r"(a) : "l"(p));
    return a;
}

// Per-buffer SMEM layout (floats): vec [JBLK*3] | sod [JBLK] | mask [JBLK]
#define BUF_FLOATS (JBLK * 3 + JBLK + JBLK)   // 2560
#define SOD_F (JBLK * 3)                      // 1536
#define MSK_F (JBLK * 4)                      // 2048

__global__ void __launch_bounds__(128)
pair_kernel(const float* __restrict__ cel,
            const int*   __restrict__ pbc,
            const int*   __restrict__ ent,
            float* __restrict__ out,
            int N, int B)
{
    __shared__ __align__(16) float sbuf[2][BUF_FLOATS];

    const int b  = blockIdx.z;
    const int i0 = blockIdx.y * I_TILE;
    const int jb = blockIdx.x * JBLK;
    const int jj = threadIdx.x * 4;      // j-index within block tile
    const int j0 = jb + jj;

    const float* c = cel + b * 9;
    const float c00 = c[0], c01 = c[1], c02 = c[2];
    const float c10 = c[3], c11 = c[4], c12 = c[5];
    const float c20 = c[6], c21 = c[7], c22 = c[8];

    const float pb0 = pbc[b * 3 + 0] ? 1.0f : 0.0f;
    const float pb1 = pbc[b * 3 + 1] ? 1.0f : 0.0f;
    const float pb2 = pbc[b * 3 + 2] ? 1.0f : 0.0f;

    const int base = b * N;

    // j-side data: loaded ONCE per block, reused for all I_TILE i's
    const float4 fx4 = *reinterpret_cast<const float4*>(g_fx + base + j0);
    const float4 fy4 = *reinterpret_cast<const float4*>(g_fy + base + j0);
    const float4 fz4 = *reinterpret_cast<const float4*>(g_fz + base + j0);
    const int4   ej4 = *reinterpret_cast<const int4*>(ent + base + j0);

    const float fjx[4] = { fx4.x, fx4.y, fx4.z, fx4.w };
    const float fjy[4] = { fy4.x, fy4.y, fy4.z, fy4.w };
    const float fjz[4] = { fz4.x, fz4.y, fz4.z, fz4.w };
    const bool  ej[4]  = { ej4.x != 0, ej4.y != 0, ej4.z != 0, ej4.w != 0 };

    const size_t NN       = (size_t)N * N;
    const size_t sod_off  = (size_t)B * NN * 3;
    const size_t mask_off = (size_t)B * NN * 4;

    #pragma unroll 1
    for (int t = 0; t < I_TILE; ++t) {
        const int i = i0 + t;
        float* buf = sbuf[t & 1];

        // backpressure: buffer (t&1) was committed at t-2; allow 1 pending group
        if (threadIdx.x == 0 && t >= 2)
            asm volatile("cp.async.bulk.wait_group.read 1;" ::: "memory");
        __syncthreads();

        const float fi0 = g_fx[base + i];
        const float fi1 = g_fy[base + i];
        const float fi2 = g_fz[base + i];
        const bool  ent_i = ent[base + i] != 0;

        float vx[4], vy[4], vz[4], sd[4], mk[4];

        #pragma unroll
        for (int k = 0; k < 4; ++k) {
            const int j = j0 + k;
            float d0 = fjx[k] - fi0;
            float d1 = fjy[k] - fi1;
            float d2 = fjz[k] - fi2;
            d0 -= rintf(d0) * pb0;   // round-half-even, matches jnp.round
            d1 -= rintf(d1) * pb1;
            d2 -= rintf(d2) * pb2;

            float v0 = d0 * c00 + d1 * c10 + d2 * c20;
            float v1 = d0 * c01 + d1 * c11 + d2 * c21;
            float v2 = d0 * c02 + d1 * c12 + d2 * c22;
            float s  = v0 * v0 + v1 * v1 + v2 * v2;

            bool ok = ent_i && ej[k] && (i != j) && (s < RC2);
            vx[k] = ok ? v0 : 0.0f;
            vy[k] = ok ? v1 : 0.0f;
            vz[k] = ok ? v2 : 0.0f;
            sd[k] = ok ? s  : 0.0f;
            mk[k] = ok ? 1.0f : 0.0f;
        }

        // stage into SMEM (cheap STS.128)
        float4* vdst = reinterpret_cast<float4*>(buf + jj * 3);
        vdst[0] = make_float4(vx[0], vy[0], vz[0], vx[1]);
        vdst[1] = make_float4(vy[1], vz[1], vx[2], vy[2]);
        vdst[2] = make_float4(vz[2], vx[3], vy[3], vz[3]);
        *reinterpret_cast<float4*>(buf + SOD_F + jj) =
            make_float4(sd[0], sd[1], sd[2], sd[3]);
        *reinterpret_cast<float4*>(buf + MSK_F + jj) =
            make_float4(mk[0], mk[1], mk[2], mk[3]);

        asm volatile("fence.proxy.async.shared::cta;" ::: "memory");
        __syncthreads();

        if (threadIdx.x == 0) {
            const size_t pair = ((size_t)base + i) * N + jb;
            uint32_t s_vec = smem_u32(buf);
            uint32_t s_sod = smem_u32(buf + SOD_F);
            uint32_t s_msk = smem_u32(buf + MSK_F);
            float* g_vec = out + pair * 3;
            float* g_sod = out + sod_off + pair;
            float* g_msk = out + mask_off + pair;

            asm volatile(
                "cp.async.bulk.global.shared::cta.bulk_group [%0], [%1], %2;"
                :: "l"(g_vec), "r"(s_vec), "r"(JBLK * 3 * 4) : "memory");
            asm volatile(
                "cp.async.bulk.global.shared::cta.bulk_group [%0], [%1], %2;"
                :: "l"(g_sod), "r"(s_sod), "r"(JBLK * 4) : "memory");
            asm volatile(
                "cp.async.bulk.global.shared::cta.bulk_group [%0], [%1], %2;"
                :: "l"(g_msk), "r"(s_msk), "r"(JBLK * 4) : "memory");
            asm volatile("cp.async.bulk.commit_group;" ::: "memory");
        }
    }

    // SMEM must stay alive until TMA reads complete
    if (threadIdx.x == 0)
        asm volatile("cp.async.bulk.wait_group.read 0;" ::: "memory");
    __syncthreads();
}

extern "C" void kernel_launch(void* const* d_in, const int* in_sizes, int n_in,
                              void* d_out, int out_size)
{
    const float* pos = (const float*)d_in[0];
    const float* cel = (const float*)d_in[1];
    const int*   pbc = (const int*)  d_in[2];
    const int*   ent = (const int*)  d_in[3];
    float* out = (float*)d_out;

    const int B = in_sizes[1] / 9;          // cel_mat has B*9 elements
    const int N = in_sizes[3] / B;          // ent has B*N elements

    {
        int total = B * N;
        int threads = 256;
        int blocks = (total + threads - 1) / threads;
        frac_kernel<<<blocks, threads>>>(pos, cel, N, B);
    }
    {
        dim3 threads(128, 1, 1);
        dim3 blocks(N / JBLK, N / I_TILE, B);
        pair_kernel<<<blocks, threads>>>(cel, pbc, ent, out, N, B);
    }
}